// round 2
// baseline (speedup 1.0000x reference)
#include <cuda_runtime.h>

// SWAP gate, DIM=2, C=0, T=1, WIRES=12 -> D=4096, BATCH=1024.
// out[k, :] = x[swap_bits_10_11(k), :] for both planes.
// Row bits 10/11 == flat-vec-index bits 18/19 (256 float4 per row).
// Latency-hiding version: 4 float4 per plane per thread, front-batched
// loads (MLP=8 per thread).

#define D_DIM   4096
#define BATCH   1024
#define VEC_PER_ROW (BATCH / 4)          // 256 float4 per row
#define TOTAL_VEC (D_DIM * VEC_PER_ROW)  // 1,048,576 float4 per plane
#define VPT 4                            // float4 per plane per thread
#define TPB 256

__global__ void __launch_bounds__(TPB) swap_gather_kernel(
    const float4* __restrict__ xr,
    const float4* __restrict__ xi,
    float4* __restrict__ out)   // [2, D, BATCH] as float4
{
    const unsigned base = blockIdx.x * (TPB * VPT) + threadIdx.x;

    float4 r[VPT], im[VPT];
    unsigned dst[VPT];

#pragma unroll
    for (int k = 0; k < VPT; k++) {
        unsigned idx = base + k * TPB;
        // swap bits 18 and 19 of the flat float4 index (== row bits 10/11)
        unsigned diff = ((idx >> 18) ^ (idx >> 19)) & 1u;
        unsigned src  = idx ^ (diff * 0xC0000u);
        dst[k] = idx;
        r[k]  = xr[src];
        im[k] = xi[src];
    }

#pragma unroll
    for (int k = 0; k < VPT; k++) {
        out[dst[k]] = r[k];
        out[TOTAL_VEC + dst[k]] = im[k];
    }
}

extern "C" void kernel_launch(void* const* d_in, const int* in_sizes, int n_in,
                              void* d_out, int out_size) {
    const float4* xr = (const float4*)d_in[0];
    const float4* xi = (const float4*)d_in[1];
    // d_in[2] = U (permutation) — closed form, unused.
    float4* out = (float4*)d_out;

    dim3 grid(TOTAL_VEC / (TPB * VPT));  // 1024 blocks
    dim3 block(TPB);
    swap_gather_kernel<<<grid, block>>>(xr, xi, out);
}